// round 9
// baseline (speedup 1.0000x reference)
#include <cuda_runtime.h>
#include <cuda_fp16.h>
#include <cstdint>

#define N_IMG 16
#define C_IN  256
#define HW    128
#define C_OUT 128
#define HALO  130

// Scratch (module-load allocated; zero-initialized => halo stays zero forever)
__device__ __align__(1024) __half g_xb[(size_t)N_IMG * HALO * HALO * C_IN];
__device__ __align__(16) uint2 g_wfrag[36 * 4 * 16 * 32];   // [chunk][kt][ntile][lane]
__device__ float g_alpha[C_OUT];

__device__ __forceinline__ float sgnf(float v) {
    return (v > 0.f) ? 1.f : ((v < 0.f) ? -1.f : 0.f);
}
__device__ __forceinline__ uint16_t sgn_h(float v) {   // f16 bits of sign()
    return (v > 0.f) ? 0x3C00u : ((v < 0.f) ? 0xBC00u : 0u);
}

// ---------------------------------------------------------------------------
// Kernel 1: sign(x) NCHW f32 -> NHWC f16 with +1 halo offset (zero padding)
// 64c x 32w tiles; __half2 stores -> fully coalesced 128B write transactions.
// ---------------------------------------------------------------------------
__global__ void pack_x_kernel(const float* __restrict__ x) {
    __shared__ float tile[64][33];
    int nh = blockIdx.z;              // n*128 + h
    int n = nh >> 7, h = nh & 127;
    int wt = blockIdx.y;              // 0..3  (w tile of 32)
    int ct = blockIdx.x;              // 0..3  (c tile of 64)
    int tx = threadIdx.x, ty = threadIdx.y;

#pragma unroll
    for (int j = 0; j < 8; j++) {
        int cl = ty + j * 8;          // 0..63
        float v = x[(((size_t)(n * C_IN + ct * 64 + cl)) * HW + h) * HW + wt * 32 + tx];
        tile[cl][tx] = sgnf(v);
    }
    __syncthreads();
#pragma unroll
    for (int j = 0; j < 4; j++) {
        int wl = ty + j * 8;          // 0..31
        __half2 hv = __floats2half2_rn(tile[tx * 2][wl], tile[tx * 2 + 1][wl]);
        size_t dsth2 = ((((size_t)n * HALO + (h + 1)) * HALO + (wt * 32 + wl + 1)) * C_IN
                        + ct * 64) >> 1;
        reinterpret_cast<__half2*>(g_xb)[dsth2 + tx] = hv;
    }
}

// ---------------------------------------------------------------------------
// Kernel 2: sign(W) OIHW -> mma.m16n8k16 B-fragment order (f16)
// chunk = ky*12 + kx*4 + cc
// ---------------------------------------------------------------------------
__global__ void pack_w_kernel(const float* __restrict__ w) {
    int g = blockIdx.x * 256 + threadIdx.x;
    if (g >= 36 * 4 * 16 * 32) return;
    int lane  = g & 31;
    int nt    = (g >> 5) & 15;   // global n-tile (8 couts)
    int kt    = (g >> 9) & 3;    // k-tile (16 ci) within 64-chunk
    int chunk = g >> 11;         // 0..35: (ky,kx,cc)
    int ky = chunk / 12, kx = (chunk / 4) % 3, cc = chunk & 3;

    int ci0 = cc * 64 + kt * 16 + (lane & 3) * 2;
    int co  = nt * 8 + (lane >> 2);

    auto widx = [&](int ci) { return (((size_t)co * C_IN + ci) * 3 + ky) * 3 + kx; };
    uint32_t lo = (uint32_t)sgn_h(w[widx(ci0)])
                | ((uint32_t)sgn_h(w[widx(ci0 + 1)]) << 16);
    uint32_t hi = (uint32_t)sgn_h(w[widx(ci0 + 8)])
                | ((uint32_t)sgn_h(w[widx(ci0 + 9)]) << 16);
    g_wfrag[g] = make_uint2(lo, hi);
}

// ---------------------------------------------------------------------------
// Kernel 3: alpha[co] = mean |W[co,:,:,:]|
// ---------------------------------------------------------------------------
__global__ void alpha_kernel(const float* __restrict__ w) {
    __shared__ float red[256];
    int co = blockIdx.x;
    float s = 0.f;
    for (int i = threadIdx.x; i < 2304; i += 256)
        s += fabsf(w[(size_t)co * 2304 + i]);
    red[threadIdx.x] = s;
    __syncthreads();
    for (int o = 128; o > 0; o >>= 1) {
        if (threadIdx.x < o) red[threadIdx.x] += red[threadIdx.x + o];
        __syncthreads();
    }
    if (threadIdx.x == 0) g_alpha[co] = red[0] / 2304.f;
}

// ---------------------------------------------------------------------------
// Kernel 4: f16 implicit-GEMM conv. CTA = one output row (n,h).
//   M=128, N=128, K = 12 A-stages (ky,cc) x 12 (kx,kt) steps x 16 ci.
//   A tile = 130 px x 64 ci reused by 3 kx via +kx*144B shift.
//   5-stage A ring, 1 barrier/stage, A-fragment double buffering,
//   B in registers with per-kt spread reload. 2 CTAs/SM.
// ---------------------------------------------------------------------------
#define A_PAD_HALVES 72          // 64 ci + 8 pad -> 144B row stride
#define A_ROWS 130
#define ASZ (A_ROWS * A_PAD_HALVES * 2)   // 18720
#define STAGES 5
#define SMEM_DYN (STAGES * ASZ)           // 93600

__device__ __forceinline__ void issue_A(char* smem, int stage, int tid,
                                        int n, int h, int s) {
    int ky = s >> 2, cc = s & 3;
    char* sA = smem + stage * ASZ;
    const __half* gx = &g_xb[(((size_t)n * HALO + h + ky) * HALO) * C_IN + cc * 64];
#pragma unroll
    for (int v = 0; v < 5; v++) {
        int u = tid + v * 256;            // 1040 units of 16B (130 rows x 8)
        if (u < A_ROWS * 8) {
            int row = u >> 3, seg = u & 7;
            uint32_t sa = (uint32_t)__cvta_generic_to_shared(sA + row * 144 + seg * 16);
            const void* ga = gx + (size_t)row * C_IN + seg * 8;
            asm volatile("cp.async.cg.shared.global [%0], [%1], 16;\n" :: "r"(sa), "l"(ga));
        }
    }
    asm volatile("cp.async.commit_group;\n");
}

#define LDSM4(dst, sAp, KX, KT) do {                                           \
    _Pragma("unroll")                                                          \
    for (int mt = 0; mt < 4; mt++) {                                           \
        uint32_t addr = (uint32_t)__cvta_generic_to_shared(                    \
            (sAp) + ((wm * 64 + mt * 16 + rl + (KX)) * A_PAD_HALVES            \
                     + (KT) * 16 + cl2) * 2);                                  \
        asm volatile(                                                          \
            "ldmatrix.sync.aligned.m8n8.x4.shared.b16 {%0,%1,%2,%3}, [%4];"    \
            : "=r"((dst)[mt][0]), "=r"((dst)[mt][1]),                          \
              "=r"((dst)[mt][2]), "=r"((dst)[mt][3])                           \
            : "r"(addr));                                                      \
    }                                                                          \
} while (0)

__global__ void __launch_bounds__(256, 2) conv_kernel(float* __restrict__ out) {
    extern __shared__ char smem[];
    int tid = threadIdx.x;
    int lane = tid & 31, wid = tid >> 5;
    int wm = wid >> 2;        // 0..1 : 64-row M slab
    int wn = wid & 3;         // 0..3 : 32-col N slab
    int h = blockIdx.x, n = blockIdx.y;

    uint32_t acc[4][4][2];    // f16x2 accumulators
#pragma unroll
    for (int a = 0; a < 4; a++)
#pragma unroll
        for (int b = 0; b < 4; b++) { acc[a][b][0] = 0u; acc[a][b][1] = 0u; }

    // B fragments for step 0 (chunk 0 = ky0,kx0,cc0), straight from gmem
    uint2 bfr[4][4];          // [kt][nt]
    {
        const uint2* gB = g_wfrag + (size_t)(wn * 4) * 32 + lane;
#pragma unroll
        for (int kt = 0; kt < 4; kt++)
#pragma unroll
            for (int nt = 0; nt < 4; nt++)
                bfr[kt][nt] = gB[(kt * 16 + nt) * 32];
    }

    issue_A(smem, 0, tid, n, h, 0);
    issue_A(smem, 1, tid, n, h, 1);
    issue_A(smem, 2, tid, n, h, 2);
    issue_A(smem, 3, tid, n, h, 3);

    int rl  = lane & 15;            // ldmatrix row-within-16
    int cl2 = (lane >> 4) * 8;      // ldmatrix col half-select

    uint32_t afr[2][4][4];          // double-buffered A fragments

    for (int s = 0; s < 12; s++) {
        asm volatile("cp.async.wait_group 3;\n");
        __syncthreads();

        const char* sA = smem + (s % 5) * ASZ;

        // Refill ring: stage (s+4)%5 == (s-1)%5, consumed at s-1; every warp
        // passed this iteration's barrier, so the overwrite is safe.
        if (s + 4 < 12)
            issue_A(smem, (s + 4) % 5, tid, n, h, s + 4);
        else
            asm volatile("cp.async.commit_group;\n");   // keep wait_group accounting

        // Per-stage chunk bases for B reloads (chunk = ky*12 + kx*4 + cc)
        int chS = (s >> 2) * 12 + (s & 3);              // this stage, kx term added later
        int chN = ((s + 1) >> 2) * 12 + ((s + 1) & 3);  // next stage, kx=0

        // Prefetch A fragments for step 0 (single exposed LDSM window/stage)
        LDSM4(afr[0], sA, 0, 0);

#pragma unroll
        for (int kk = 0; kk < 12; kk++) {
            int kx = kk >> 2, kt = kk & 3;

            // Prefetch next step's A fragments (hidden under this step's MMAs)
            if (kk < 11)
                LDSM4(afr[(kk + 1) & 1], sA, (kk + 1) >> 2, (kk + 1) & 3);

#pragma unroll
            for (int mt = 0; mt < 4; mt++)
#pragma unroll
                for (int nt = 0; nt < 4; nt++)
                    asm volatile(
                        "mma.sync.aligned.m16n8k16.row.col.f16.f16.f16.f16 "
                        "{%0,%1}, {%2,%3,%4,%5}, {%6,%7}, {%0,%1};"
                        : "+r"(acc[mt][nt][0]), "+r"(acc[mt][nt][1])
                        : "r"(afr[kk & 1][mt][0]), "r"(afr[kk & 1][mt][1]),
                          "r"(afr[kk & 1][mt][2]), "r"(afr[kk & 1][mt][3]),
                          "r"(bfr[kt][nt].x), "r"(bfr[kt][nt].y));

            // bfr[kt] is now dead for this chunk; reload it for the next kx
            // (or next stage's kx=0), 4 steps (~500 cyc) before its next use.
            if (!(s == 11 && kx == 2)) {
                int ch = (kx < 2) ? (chS + (kx + 1) * 4) : chN;
                const uint2* gBn = g_wfrag + (size_t)ch * 2048
                                 + (size_t)(kt * 16 + wn * 4) * 32 + lane;
#pragma unroll
                for (int nt = 0; nt < 4; nt++)
                    bfr[kt][nt] = gBn[nt * 32];
            }
        }
    }

    // Epilogue: f16 acc -> smem [co][w] (pad 132) as f32, then coalesced
    // NCHW store with alpha[w] (reference broadcasts alpha along width axis)
    __syncthreads();
    float* so = (float*)smem;
#pragma unroll
    for (int mt = 0; mt < 4; mt++) {
        int r0 = wm * 64 + mt * 16 + (lane >> 2);   // w index
#pragma unroll
        for (int nt = 0; nt < 4; nt++) {
            int c0 = wn * 32 + nt * 8 + (lane & 3) * 2;   // co index
            float2 f0 = __half22float2(*reinterpret_cast<__half2*>(&acc[mt][nt][0]));
            float2 f1 = __half22float2(*reinterpret_cast<__half2*>(&acc[mt][nt][1]));
            so[(size_t)c0 * 132 + r0]           = f0.x;
            so[(size_t)(c0 + 1) * 132 + r0]     = f0.y;
            so[(size_t)c0 * 132 + r0 + 8]       = f1.x;
            so[(size_t)(c0 + 1) * 132 + r0 + 8] = f1.y;
        }
    }
    __syncthreads();

    int w = tid & 127;
    float al = g_alpha[w];
    float* ob = out + ((size_t)n * C_OUT * HW + (size_t)h) * HW;   // + co*HW*HW + w
#pragma unroll 4
    for (int k = 0; k < 64; k++) {
        int co = (tid >> 7) + k * 2;
        ob[(size_t)co * HW * HW + w] = so[(size_t)co * 132 + w] * al;
    }
}

// ---------------------------------------------------------------------------
extern "C" void kernel_launch(void* const* d_in, const int* in_sizes, int n_in,
                              void* d_out, int out_size) {
    (void)in_sizes; (void)n_in; (void)out_size;
    const float* x = (const float*)d_in[0];
    const float* w = (const float*)d_in[1];
    float* out = (float*)d_out;

    cudaFuncSetAttribute(conv_kernel,
                         cudaFuncAttributeMaxDynamicSharedMemorySize, SMEM_DYN);

    dim3 pg(4, 4, N_IMG * HW);
    dim3 pb(32, 8);
    pack_x_kernel<<<pg, pb>>>(x);
    pack_w_kernel<<<288, 256>>>(w);
    alpha_kernel<<<C_OUT, 256>>>(w);
    conv_kernel<<<dim3(HW, N_IMG), 256, SMEM_DYN>>>(out);
}